// round 3
// baseline (speedup 1.0000x reference)
#include <cuda_runtime.h>
#include <cstdint>

#define NNODES_MAX 100000
#define NFEAT 128

// Scratch (allocation-free rule: __device__ globals)
__device__ float g_h[(size_t)NNODES_MAX * NFEAT];   // h = x @ W
__device__ float g_deg[NNODES_MAX];                 // degree, then dinv in-place

// ---------------------------------------------------------------------------
// K1: deg[n] = 1 (self loop)
__global__ void k_deg_init(int n) {
    int i = blockIdx.x * blockDim.x + threadIdx.x;
    if (i < n) g_deg[i] = 1.0f;
}

// K2: deg[dst] += 1 per edge  (edge_index is int32: [2, E])
__global__ void k_deg_acc(const int* __restrict__ ei, int E) {
    int e = blockIdx.x * blockDim.x + threadIdx.x;
    if (e < E) {
        int d = ei[E + e];
        atomicAdd(&g_deg[d], 1.0f);
    }
}

// K3: deg -> rsqrt(deg) in place (deg >= 1 always due to self loops)
__global__ void k_dinv(int n) {
    int i = blockIdx.x * blockDim.x + threadIdx.x;
    if (i < n) g_deg[i] = rsqrtf(g_deg[i]);
}

// ---------------------------------------------------------------------------
// K4: GEMM h = x @ W   (M x 128) @ (128 x 128), fp32, packed f32x2 FFMA
#define BM 64
#define BN 128
#define BK 16
#define TM 8
#define TN 8

__global__ __launch_bounds__(128) void k_gemm(const float* __restrict__ X,
                                              const float* __restrict__ W,
                                              int M) {
    __shared__ float As[BM][BK + 1];   // +1 pad
    __shared__ float Bs[BK][BN];

    int tid = threadIdx.x;
    int m0  = blockIdx.x * BM;
    int tmr = (tid >> 4) * TM;   // 0..56
    int tnc = (tid & 15) * TN;   // 0..120

    unsigned long long acc[TM][TN / 2];
#pragma unroll
    for (int i = 0; i < TM; i++)
#pragma unroll
        for (int j = 0; j < TN / 2; j++) acc[i][j] = 0ULL;

    for (int k0 = 0; k0 < NFEAT; k0 += BK) {
        // Load A tile: 64 x 16 floats = 256 float4, 2 per thread
#pragma unroll
        for (int j = 0; j < 2; j++) {
            int idx = tid + j * 128;       // 0..255
            int r   = idx >> 2;            // 0..63
            int c4  = idx & 3;             // 0..3
            float4 v = make_float4(0.f, 0.f, 0.f, 0.f);
            int gr = m0 + r;
            if (gr < M)
                v = *(const float4*)(X + (size_t)gr * NFEAT + k0 + c4 * 4);
            As[r][c4 * 4 + 0] = v.x;
            As[r][c4 * 4 + 1] = v.y;
            As[r][c4 * 4 + 2] = v.z;
            As[r][c4 * 4 + 3] = v.w;
        }
        // Load B tile: 16 x 128 floats = 512 float4, 4 per thread
#pragma unroll
        for (int j = 0; j < 4; j++) {
            int idx = tid + j * 128;       // 0..511
            int r   = idx >> 5;            // 0..15
            int c4  = idx & 31;            // 0..31
            *(float4*)&Bs[r][c4 * 4] =
                *(const float4*)(W + (size_t)(k0 + r) * NFEAT + c4 * 4);
        }
        __syncthreads();

#pragma unroll
        for (int k = 0; k < BK; k++) {
            unsigned long long apair[TM];
#pragma unroll
            for (int i = 0; i < TM; i++) {
                float a = As[tmr + i][k];
                asm("mov.b64 %0, {%1,%1};" : "=l"(apair[i]) : "f"(a));
            }
            unsigned long long bpair[TN / 2];
#pragma unroll
            for (int j = 0; j < TN / 2; j++)
                bpair[j] = *(const unsigned long long*)&Bs[k][tnc + 2 * j];
#pragma unroll
            for (int i = 0; i < TM; i++)
#pragma unroll
                for (int j = 0; j < TN / 2; j++)
                    asm("fma.rn.f32x2 %0, %1, %2, %0;"
                        : "+l"(acc[i][j])
                        : "l"(apair[i]), "l"(bpair[j]));
        }
        __syncthreads();
    }

    // Store h
#pragma unroll
    for (int i = 0; i < TM; i++) {
        int gr = m0 + tmr + i;
        if (gr < M) {
            float* dst = g_h + (size_t)gr * NFEAT + tnc;
#pragma unroll
            for (int j = 0; j < TN / 2; j++) {
                float lo, hi;
                asm("mov.b64 {%0,%1}, %2;" : "=f"(lo), "=f"(hi) : "l"(acc[i][j]));
                dst[2 * j]     = lo;
                dst[2 * j + 1] = hi;
            }
        }
    }
}

// ---------------------------------------------------------------------------
// K5: out[n][:] = b[:] + h[n][:] * dinv[n]^2   (self-loop term + bias, non-atomic init)
__global__ void k_init_out(const float* __restrict__ b, float* __restrict__ out, int n) {
    int idx = blockIdx.x * blockDim.x + threadIdx.x;   // over n*32 float4s
    if (idx >= n * 32) return;
    int node = idx >> 5;
    int c4   = idx & 31;
    float di = g_deg[node];          // dinv
    float wsl = di * di;             // 1/deg
    float4 hv = *((const float4*)(g_h + (size_t)node * NFEAT) + c4);
    float4 bv = *((const float4*)b + c4);
    float4 o;
    o.x = bv.x + hv.x * wsl;
    o.y = bv.y + hv.y * wsl;
    o.z = bv.z + hv.z * wsl;
    o.w = bv.w + hv.w * wsl;
    *((float4*)(out + (size_t)node * NFEAT) + c4) = o;
}

// ---------------------------------------------------------------------------
// K6: edge scatter, one warp per edge, red.global.add.v4.f32
__global__ __launch_bounds__(256) void k_scatter(const int* __restrict__ ei,
                                                 float* __restrict__ out, int E) {
    int warp = blockIdx.x * (blockDim.x >> 5) + (threadIdx.x >> 5);
    int lane = threadIdx.x & 31;
    if (warp >= E) return;
    int s = ei[warp];
    int d = ei[E + warp];
    float w = g_deg[s] * g_deg[d];   // dinv[src]*dinv[dst]
    float4 v = *((const float4*)(g_h + (size_t)s * NFEAT) + lane);
    float* op = out + (size_t)d * NFEAT + lane * 4;
    asm volatile("red.global.add.v4.f32 [%0], {%1,%2,%3,%4};"
                 :: "l"(op), "f"(v.x * w), "f"(v.y * w), "f"(v.z * w), "f"(v.w * w)
                 : "memory");
}

// ---------------------------------------------------------------------------
extern "C" void kernel_launch(void* const* d_in, const int* in_sizes, int n_in,
                              void* d_out, int out_size) {
    const float* x  = (const float*)d_in[0];
    const int*   ei = (const int*)d_in[1];
    const float* w  = (const float*)d_in[2];
    const float* b  = (const float*)d_in[3];
    float* out = (float*)d_out;

    int N = in_sizes[0] / NFEAT;
    int E = in_sizes[1] / 2;

    k_deg_init<<<(N + 255) / 256, 256>>>(N);
    k_deg_acc<<<(E + 255) / 256, 256>>>(ei, E);
    k_dinv<<<(N + 255) / 256, 256>>>(N);
    k_gemm<<<(N + BM - 1) / BM, 128>>>(x, w, N);
    k_init_out<<<(N * 32 + 255) / 256, 256>>>(b, out, N);
    k_scatter<<<(E + 7) / 8, 256>>>(ei, out, E);
}

// round 4
// speedup vs baseline: 1.7634x; 1.7634x over previous
#include <cuda_runtime.h>
#include <cstdint>

#define NNODES_MAX 100000
#define NEDGES_MAX 2000000
#define NFEAT 128

// Scratch (allocation-free rule: __device__ globals)
__device__ float g_h[(size_t)NNODES_MAX * NFEAT];   // h = x @ W
__device__ float g_dinv[NNODES_MAX];
__device__ int   g_cnt[NNODES_MAX];                 // in-degree (excl. self loop)
__device__ int   g_scan[NNODES_MAX];
__device__ int   g_part[512];
__device__ int   g_off[NNODES_MAX];
__device__ int   g_cursor[NNODES_MAX];
__device__ int   g_csr[NEDGES_MAX];                 // src ids grouped by dst

// ---------------------------------------------------------------------------
__global__ void k_zero_cnt(int n) {
    int i = blockIdx.x * blockDim.x + threadIdx.x;
    if (i < n) g_cnt[i] = 0;
}

__global__ void k_count(const int* __restrict__ ei, int E) {
    int e = blockIdx.x * blockDim.x + threadIdx.x;
    if (e < E) atomicAdd(&g_cnt[ei[E + e]], 1);
}

__global__ void k_dinv(int n) {
    int i = blockIdx.x * blockDim.x + threadIdx.x;
    if (i < n) g_dinv[i] = rsqrtf((float)g_cnt[i] + 1.0f);
}

// ---------------------------------------------------------------------------
// 3-phase exclusive scan of g_cnt -> g_off (and g_cursor copy)
__global__ void k_scan1(int n) {
    __shared__ int sh[256];
    int t = threadIdx.x;
    int i = blockIdx.x * 256 + t;
    int v = (i < n) ? g_cnt[i] : 0;
    sh[t] = v;
    __syncthreads();
#pragma unroll
    for (int ofs = 1; ofs < 256; ofs <<= 1) {
        int x = (t >= ofs) ? sh[t - ofs] : 0;
        __syncthreads();
        sh[t] += x;
        __syncthreads();
    }
    if (i < n) g_scan[i] = sh[t];
    if (t == 255) g_part[blockIdx.x] = sh[255];
}

__global__ void k_scan2(int nb) {
    __shared__ int sh[512];
    int t = threadIdx.x;
    int v = (t < nb) ? g_part[t] : 0;
    sh[t] = v;
    __syncthreads();
#pragma unroll
    for (int ofs = 1; ofs < 512; ofs <<= 1) {
        int x = (t >= ofs) ? sh[t - ofs] : 0;
        __syncthreads();
        sh[t] += x;
        __syncthreads();
    }
    if (t < nb) g_part[t] = sh[t];
}

__global__ void k_scan3(int n) {
    int i = blockIdx.x * blockDim.x + threadIdx.x;
    if (i >= n) return;
    int b = i >> 8;
    int off = g_scan[i] - g_cnt[i] + (b > 0 ? g_part[b - 1] : 0);
    g_off[i] = off;
    g_cursor[i] = off;
}

__global__ void k_csr(const int* __restrict__ ei, int E) {
    int e = blockIdx.x * blockDim.x + threadIdx.x;
    if (e >= E) return;
    int s = ei[e];
    int d = ei[E + e];
    int pos = atomicAdd(&g_cursor[d], 1);
    g_csr[pos] = s;
}

// ---------------------------------------------------------------------------
// GEMM h = x @ W  (M x 128) @ (128 x 128), fp32 f32x2 FFMA, A transposed in smem
#define BM 64
#define BN 128
#define BK 16
#define TM 8
#define TN 8

__global__ __launch_bounds__(128) void k_gemm(const float* __restrict__ X,
                                              const float* __restrict__ W,
                                              int M) {
    __shared__ float Ast[BK][BM + 4];   // transposed A tile, pad 4 (row = 272B)
    __shared__ float Bs[BK][BN];

    int tid = threadIdx.x;
    int m0  = blockIdx.x * BM;
    int tmr = (tid >> 4) * TM;   // 0..56
    int tnc = (tid & 15) * TN;   // 0..120

    unsigned long long acc[TM][TN / 2];
#pragma unroll
    for (int i = 0; i < TM; i++)
#pragma unroll
        for (int j = 0; j < TN / 2; j++) acc[i][j] = 0ULL;

    for (int k0 = 0; k0 < NFEAT; k0 += BK) {
        // A tile: 64 rows x 16 cols = 256 float4, 2 per thread, store transposed
#pragma unroll
        for (int j = 0; j < 2; j++) {
            int idx = tid + j * 128;       // 0..255
            int r   = idx >> 2;            // 0..63
            int c4  = idx & 3;             // 0..3
            float4 v = make_float4(0.f, 0.f, 0.f, 0.f);
            int gr = m0 + r;
            if (gr < M)
                v = *(const float4*)(X + (size_t)gr * NFEAT + k0 + c4 * 4);
            Ast[c4 * 4 + 0][r] = v.x;
            Ast[c4 * 4 + 1][r] = v.y;
            Ast[c4 * 4 + 2][r] = v.z;
            Ast[c4 * 4 + 3][r] = v.w;
        }
        // B tile: 16 x 128 = 512 float4, 4 per thread
#pragma unroll
        for (int j = 0; j < 4; j++) {
            int idx = tid + j * 128;       // 0..511
            int r   = idx >> 5;            // 0..15
            int c4  = idx & 31;            // 0..31
            *(float4*)&Bs[r][c4 * 4] =
                *(const float4*)(W + (size_t)(k0 + r) * NFEAT + c4 * 4);
        }
        __syncthreads();

#pragma unroll
        for (int k = 0; k < BK; k++) {
            float4 a0 = *(const float4*)&Ast[k][tmr];
            float4 a1 = *(const float4*)&Ast[k][tmr + 4];
            float4 b0 = *(const float4*)&Bs[k][tnc];
            float4 b1 = *(const float4*)&Bs[k][tnc + 4];

            unsigned long long apair[TM];
            float av[TM] = {a0.x, a0.y, a0.z, a0.w, a1.x, a1.y, a1.z, a1.w};
#pragma unroll
            for (int i = 0; i < TM; i++)
                asm("mov.b64 %0, {%1,%1};" : "=l"(apair[i]) : "f"(av[i]));

            unsigned long long bpair[TN / 2];
            asm("mov.b64 %0, {%1,%2};" : "=l"(bpair[0]) : "f"(b0.x), "f"(b0.y));
            asm("mov.b64 %0, {%1,%2};" : "=l"(bpair[1]) : "f"(b0.z), "f"(b0.w));
            asm("mov.b64 %0, {%1,%2};" : "=l"(bpair[2]) : "f"(b1.x), "f"(b1.y));
            asm("mov.b64 %0, {%1,%2};" : "=l"(bpair[3]) : "f"(b1.z), "f"(b1.w));

#pragma unroll
            for (int i = 0; i < TM; i++)
#pragma unroll
                for (int j = 0; j < TN / 2; j++)
                    asm("fma.rn.f32x2 %0, %1, %2, %0;"
                        : "+l"(acc[i][j])
                        : "l"(apair[i]), "l"(bpair[j]));
        }
        __syncthreads();
    }

#pragma unroll
    for (int i = 0; i < TM; i++) {
        int gr = m0 + tmr + i;
        if (gr < M) {
            float* dst = g_h + (size_t)gr * NFEAT + tnc;
            float o[TN];
#pragma unroll
            for (int j = 0; j < TN / 2; j++)
                asm("mov.b64 {%0,%1}, %2;" : "=f"(o[2 * j]), "=f"(o[2 * j + 1])
                    : "l"(acc[i][j]));
            *(float4*)(dst)     = make_float4(o[0], o[1], o[2], o[3]);
            *(float4*)(dst + 4) = make_float4(o[4], o[5], o[6], o[7]);
        }
    }
}

// ---------------------------------------------------------------------------
// Gather: one warp per dst node, accumulate in registers, single coalesced write.
__global__ __launch_bounds__(256) void k_gather(const float* __restrict__ b,
                                                float* __restrict__ out, int N) {
    int node = blockIdx.x * 8 + (threadIdx.x >> 5);
    if (node >= N) return;
    int lane = threadIdx.x & 31;

    int base = g_off[node];
    int cnt  = g_cnt[node];
    float dd = g_dinv[node];

    float4 bv = ((const float4*)b)[lane];
    float4 hv = ((const float4*)(g_h + (size_t)node * NFEAT))[lane];
    float w0  = dd * dd;   // self-loop weight = 1/deg
    float4 acc;
    acc.x = bv.x + hv.x * w0;
    acc.y = bv.y + hv.y * w0;
    acc.z = bv.z + hv.z * w0;
    acc.w = bv.w + hv.w * w0;

    int i = 0;
    // unroll-2 with prefetch for MLP
    for (; i + 2 <= cnt; i += 2) {
        int s0 = g_csr[base + i];
        int s1 = g_csr[base + i + 1];
        float wA = g_dinv[s0] * dd;
        float wB = g_dinv[s1] * dd;
        float4 vA = ((const float4*)(g_h + (size_t)s0 * NFEAT))[lane];
        float4 vB = ((const float4*)(g_h + (size_t)s1 * NFEAT))[lane];
        acc.x += vA.x * wA; acc.y += vA.y * wA;
        acc.z += vA.z * wA; acc.w += vA.w * wA;
        acc.x += vB.x * wB; acc.y += vB.y * wB;
        acc.z += vB.z * wB; acc.w += vB.w * wB;
    }
    if (i < cnt) {
        int s0 = g_csr[base + i];
        float wA = g_dinv[s0] * dd;
        float4 vA = ((const float4*)(g_h + (size_t)s0 * NFEAT))[lane];
        acc.x += vA.x * wA; acc.y += vA.y * wA;
        acc.z += vA.z * wA; acc.w += vA.w * wA;
    }

    ((float4*)(out + (size_t)node * NFEAT))[lane] = acc;
}

// ---------------------------------------------------------------------------
extern "C" void kernel_launch(void* const* d_in, const int* in_sizes, int n_in,
                              void* d_out, int out_size) {
    const float* x  = (const float*)d_in[0];
    const int*   ei = (const int*)d_in[1];
    const float* w  = (const float*)d_in[2];
    const float* b  = (const float*)d_in[3];
    float* out = (float*)d_out;

    int N = in_sizes[0] / NFEAT;
    int E = in_sizes[1] / 2;
    int NB = (N + 255) / 256;   // scan blocks (<=512)

    k_zero_cnt<<<(N + 255) / 256, 256>>>(N);
    k_count<<<(E + 255) / 256, 256>>>(ei, E);
    k_dinv<<<(N + 255) / 256, 256>>>(N);
    k_scan1<<<NB, 256>>>(N);
    k_scan2<<<1, 512>>>(NB);
    k_scan3<<<(N + 255) / 256, 256>>>(N);
    k_csr<<<(E + 255) / 256, 256>>>(ei, E);
    k_gemm<<<(N + BM - 1) / BM, 128>>>(x, w, N);
    k_gather<<<(N + 7) / 8, 256>>>(b, out, N);
}

// round 5
// speedup vs baseline: 1.8012x; 1.0214x over previous
#include <cuda_runtime.h>
#include <cstdint>

#define NNODES_MAX 100000
#define NEDGES_MAX 2000000
#define NFEAT 128

// Scratch (allocation-free rule: __device__ globals)
__device__ float g_h[(size_t)NNODES_MAX * NFEAT];   // h' = (x @ W) * dinv[row]
__device__ float g_dinv[NNODES_MAX];
__device__ int   g_cnt[NNODES_MAX];                 // in-degree (excl. self loop)
__device__ int   g_scan[NNODES_MAX];
__device__ int   g_part[512];
__device__ int   g_off[NNODES_MAX];
__device__ int   g_cursor[NNODES_MAX];
__device__ int   g_csr[NEDGES_MAX];                 // src ids grouped by dst

// ---------------------------------------------------------------------------
__global__ void k_zero_cnt(int n) {
    int i = blockIdx.x * blockDim.x + threadIdx.x;
    if (i < n) g_cnt[i] = 0;
}

// count: 4 edges/thread via int4 (E % 4 == 0 path)
__global__ void k_count4(const int* __restrict__ ei, int E) {
    int e4 = blockIdx.x * blockDim.x + threadIdx.x;
    if (e4 * 4 >= E) return;
    int4 d = ((const int4*)(ei + E))[e4];
    atomicAdd(&g_cnt[d.x], 1);
    atomicAdd(&g_cnt[d.y], 1);
    atomicAdd(&g_cnt[d.z], 1);
    atomicAdd(&g_cnt[d.w], 1);
}
__global__ void k_count1(const int* __restrict__ ei, int E) {
    int e = blockIdx.x * blockDim.x + threadIdx.x;
    if (e < E) atomicAdd(&g_cnt[ei[E + e]], 1);
}

__global__ void k_dinv(int n) {
    int i = blockIdx.x * blockDim.x + threadIdx.x;
    if (i < n) g_dinv[i] = rsqrtf((float)g_cnt[i] + 1.0f);
}

// ---------------------------------------------------------------------------
// GEMM h' = (x @ W) * dinv  (M x 128)@(128 x 128), fp32 f32x2 FFMA, A^T in smem
#define BM 64
#define BN 128
#define BK 16
#define TM 8
#define TN 8

__global__ __launch_bounds__(128) void k_gemm(const float* __restrict__ X,
                                              const float* __restrict__ W,
                                              int M) {
    __shared__ float Ast[BK][BM + 4];
    __shared__ float Bs[BK][BN];

    int tid = threadIdx.x;
    int m0  = blockIdx.x * BM;
    int tmr = (tid >> 4) * TM;
    int tnc = (tid & 15) * TN;

    unsigned long long acc[TM][TN / 2];
#pragma unroll
    for (int i = 0; i < TM; i++)
#pragma unroll
        for (int j = 0; j < TN / 2; j++) acc[i][j] = 0ULL;

    for (int k0 = 0; k0 < NFEAT; k0 += BK) {
#pragma unroll
        for (int j = 0; j < 2; j++) {
            int idx = tid + j * 128;
            int r   = idx >> 2;
            int c4  = idx & 3;
            float4 v = make_float4(0.f, 0.f, 0.f, 0.f);
            int gr = m0 + r;
            if (gr < M)
                v = *(const float4*)(X + (size_t)gr * NFEAT + k0 + c4 * 4);
            Ast[c4 * 4 + 0][r] = v.x;
            Ast[c4 * 4 + 1][r] = v.y;
            Ast[c4 * 4 + 2][r] = v.z;
            Ast[c4 * 4 + 3][r] = v.w;
        }
#pragma unroll
        for (int j = 0; j < 4; j++) {
            int idx = tid + j * 128;
            int r   = idx >> 5;
            int c4  = idx & 31;
            *(float4*)&Bs[r][c4 * 4] =
                *(const float4*)(W + (size_t)(k0 + r) * NFEAT + c4 * 4);
        }
        __syncthreads();

#pragma unroll
        for (int k = 0; k < BK; k++) {
            float4 a0 = *(const float4*)&Ast[k][tmr];
            float4 a1 = *(const float4*)&Ast[k][tmr + 4];
            float4 b0 = *(const float4*)&Bs[k][tnc];
            float4 b1 = *(const float4*)&Bs[k][tnc + 4];

            unsigned long long apair[TM];
            float av[TM] = {a0.x, a0.y, a0.z, a0.w, a1.x, a1.y, a1.z, a1.w};
#pragma unroll
            for (int i = 0; i < TM; i++)
                asm("mov.b64 %0, {%1,%1};" : "=l"(apair[i]) : "f"(av[i]));

            unsigned long long bpair[TN / 2];
            asm("mov.b64 %0, {%1,%2};" : "=l"(bpair[0]) : "f"(b0.x), "f"(b0.y));
            asm("mov.b64 %0, {%1,%2};" : "=l"(bpair[1]) : "f"(b0.z), "f"(b0.w));
            asm("mov.b64 %0, {%1,%2};" : "=l"(bpair[2]) : "f"(b1.x), "f"(b1.y));
            asm("mov.b64 %0, {%1,%2};" : "=l"(bpair[3]) : "f"(b1.z), "f"(b1.w));

#pragma unroll
            for (int i = 0; i < TM; i++)
#pragma unroll
                for (int j = 0; j < TN / 2; j++)
                    asm("fma.rn.f32x2 %0, %1, %2, %0;"
                        : "+l"(acc[i][j])
                        : "l"(apair[i]), "l"(bpair[j]));
        }
        __syncthreads();
    }

#pragma unroll
    for (int i = 0; i < TM; i++) {
        int gr = m0 + tmr + i;
        if (gr < M) {
            float dv = g_dinv[gr];
            float* dst = g_h + (size_t)gr * NFEAT + tnc;
            float o[TN];
#pragma unroll
            for (int j = 0; j < TN / 2; j++)
                asm("mov.b64 {%0,%1}, %2;" : "=f"(o[2 * j]), "=f"(o[2 * j + 1])
                    : "l"(acc[i][j]));
            *(float4*)(dst)     = make_float4(o[0] * dv, o[1] * dv, o[2] * dv, o[3] * dv);
            *(float4*)(dst + 4) = make_float4(o[4] * dv, o[5] * dv, o[6] * dv, o[7] * dv);
        }
    }
}

// ---------------------------------------------------------------------------
// Warp-shuffle scans
__global__ void k_scan1(int n) {
    __shared__ int ws[8];
    int t = threadIdx.x, lane = t & 31, wid = t >> 5;
    int i = blockIdx.x * 256 + t;
    int x = (i < n) ? g_cnt[i] : 0;
#pragma unroll
    for (int ofs = 1; ofs < 32; ofs <<= 1) {
        int y = __shfl_up_sync(0xffffffffu, x, ofs);
        if (lane >= ofs) x += y;
    }
    if (lane == 31) ws[wid] = x;
    __syncthreads();
    if (wid == 0) {
        int y = (lane < 8) ? ws[lane] : 0;
#pragma unroll
        for (int ofs = 1; ofs < 8; ofs <<= 1) {
            int z = __shfl_up_sync(0xffffffffu, y, ofs);
            if (lane >= ofs) y += z;
        }
        if (lane < 8) ws[lane] = y;
    }
    __syncthreads();
    int incl = x + (wid > 0 ? ws[wid - 1] : 0);
    if (i < n) g_scan[i] = incl;
    if (t == 255) g_part[blockIdx.x] = incl;
}

__global__ void k_scan2(int nb) {
    __shared__ int ws[16];
    int t = threadIdx.x, lane = t & 31, wid = t >> 5;
    int x = (t < nb) ? g_part[t] : 0;
#pragma unroll
    for (int ofs = 1; ofs < 32; ofs <<= 1) {
        int y = __shfl_up_sync(0xffffffffu, x, ofs);
        if (lane >= ofs) x += y;
    }
    if (lane == 31) ws[wid] = x;
    __syncthreads();
    if (wid == 0) {
        int y = (lane < 16) ? ws[lane] : 0;
#pragma unroll
        for (int ofs = 1; ofs < 16; ofs <<= 1) {
            int z = __shfl_up_sync(0xffffffffu, y, ofs);
            if (lane >= ofs) y += z;
        }
        if (lane < 16) ws[lane] = y;
    }
    __syncthreads();
    int incl = x + (wid > 0 ? ws[wid - 1] : 0);
    if (t < nb) g_part[t] = incl;
}

__global__ void k_scan3(int n) {
    int i = blockIdx.x * blockDim.x + threadIdx.x;
    if (i >= n) return;
    int b = i >> 8;
    int off = g_scan[i] - g_cnt[i] + (b > 0 ? g_part[b - 1] : 0);
    g_off[i] = off;
    g_cursor[i] = off;
}

// CSR fill: 4 edges/thread via int4
__global__ void k_csr4(const int* __restrict__ ei, int E) {
    int e4 = blockIdx.x * blockDim.x + threadIdx.x;
    if (e4 * 4 >= E) return;
    int4 s = ((const int4*)ei)[e4];
    int4 d = ((const int4*)(ei + E))[e4];
    g_csr[atomicAdd(&g_cursor[d.x], 1)] = s.x;
    g_csr[atomicAdd(&g_cursor[d.y], 1)] = s.y;
    g_csr[atomicAdd(&g_cursor[d.z], 1)] = s.z;
    g_csr[atomicAdd(&g_cursor[d.w], 1)] = s.w;
}
__global__ void k_csr1(const int* __restrict__ ei, int E) {
    int e = blockIdx.x * blockDim.x + threadIdx.x;
    if (e >= E) return;
    g_csr[atomicAdd(&g_cursor[ei[E + e]], 1)] = ei[e];
}

// ---------------------------------------------------------------------------
// Gather: one warp per dst node; h is pre-scaled by dinv[src].
// out = (sum_src h'[src] + h'[node]) * dinv[node] + b
__global__ __launch_bounds__(256) void k_gather(const float* __restrict__ b,
                                                float* __restrict__ out, int N) {
    int node = blockIdx.x * 8 + (threadIdx.x >> 5);
    if (node >= N) return;
    int lane = threadIdx.x & 31;

    int base = g_off[node];
    int cnt  = g_cnt[node];
    float dd = g_dinv[node];

    float4 acc = ((const float4*)(g_h + (size_t)node * NFEAT))[lane];  // h'[node]

    int i = 0;
    for (; i + 4 <= cnt; i += 4) {
        int s0 = g_csr[base + i];
        int s1 = g_csr[base + i + 1];
        int s2 = g_csr[base + i + 2];
        int s3 = g_csr[base + i + 3];
        float4 v0 = ((const float4*)(g_h + (size_t)s0 * NFEAT))[lane];
        float4 v1 = ((const float4*)(g_h + (size_t)s1 * NFEAT))[lane];
        float4 v2 = ((const float4*)(g_h + (size_t)s2 * NFEAT))[lane];
        float4 v3 = ((const float4*)(g_h + (size_t)s3 * NFEAT))[lane];
        acc.x += v0.x + v1.x + v2.x + v3.x;
        acc.y += v0.y + v1.y + v2.y + v3.y;
        acc.z += v0.z + v1.z + v2.z + v3.z;
        acc.w += v0.w + v1.w + v2.w + v3.w;
    }
    for (; i < cnt; i++) {
        int s0 = g_csr[base + i];
        float4 v0 = ((const float4*)(g_h + (size_t)s0 * NFEAT))[lane];
        acc.x += v0.x; acc.y += v0.y; acc.z += v0.z; acc.w += v0.w;
    }

    float4 bv = ((const float4*)b)[lane];
    float4 o;
    o.x = bv.x + acc.x * dd;
    o.y = bv.y + acc.y * dd;
    o.z = bv.z + acc.z * dd;
    o.w = bv.w + acc.w * dd;
    ((float4*)(out + (size_t)node * NFEAT))[lane] = o;
}

// ---------------------------------------------------------------------------
extern "C" void kernel_launch(void* const* d_in, const int* in_sizes, int n_in,
                              void* d_out, int out_size) {
    const float* x  = (const float*)d_in[0];
    const int*   ei = (const int*)d_in[1];
    const float* w  = (const float*)d_in[2];
    const float* b  = (const float*)d_in[3];
    float* out = (float*)d_out;

    int N = in_sizes[0] / NFEAT;
    int E = in_sizes[1] / 2;
    int NB = (N + 255) / 256;

    k_zero_cnt<<<(N + 255) / 256, 256>>>(N);
    if ((E & 3) == 0)
        k_count4<<<(E / 4 + 255) / 256, 256>>>(ei, E);
    else
        k_count1<<<(E + 255) / 256, 256>>>(ei, E);
    k_dinv<<<(N + 255) / 256, 256>>>(N);
    k_gemm<<<(N + BM - 1) / BM, 128>>>(x, w, N);   // launch idx 3 -> profiled
    k_scan1<<<NB, 256>>>(N);
    k_scan2<<<1, 512>>>(NB);
    k_scan3<<<(N + 255) / 256, 256>>>(N);
    if ((E & 3) == 0)
        k_csr4<<<(E / 4 + 255) / 256, 256>>>(ei, E);
    else
        k_csr1<<<(E + 255) / 256, 256>>>(ei, E);
    k_gather<<<(N + 7) / 8, 256>>>(b, out, N);
}

// round 7
// speedup vs baseline: 2.1966x; 1.2195x over previous
#include <cuda_runtime.h>
#include <cuda_fp16.h>
#include <cstdint>

#define NNODES_MAX 100000
#define NEDGES_MAX 2000000
#define NFEAT 128

// Scratch (allocation-free rule: __device__ globals)
__device__ __half2 g_hh[(size_t)NNODES_MAX * (NFEAT / 2)];  // h' = (x@W)*dinv, fp16
__device__ float g_dinv[NNODES_MAX];
__device__ int   g_cnt[NNODES_MAX];
__device__ int   g_scan[NNODES_MAX];
__device__ int   g_part[512];
__device__ int   g_off[NNODES_MAX];
__device__ int   g_cursor[NNODES_MAX];
__device__ int   g_csr[NEDGES_MAX];

// ---------------------------------------------------------------------------
__global__ void k_zero_cnt(int n) {
    int i = blockIdx.x * blockDim.x + threadIdx.x;
    if (i < n) g_cnt[i] = 0;
}

__global__ void k_count4(const int* __restrict__ ei, int E) {
    int e4 = blockIdx.x * blockDim.x + threadIdx.x;
    if (e4 * 4 >= E) return;
    int4 d = ((const int4*)(ei + E))[e4];
    atomicAdd(&g_cnt[d.x], 1);
    atomicAdd(&g_cnt[d.y], 1);
    atomicAdd(&g_cnt[d.z], 1);
    atomicAdd(&g_cnt[d.w], 1);
}
__global__ void k_count1(const int* __restrict__ ei, int E) {
    int e = blockIdx.x * blockDim.x + threadIdx.x;
    if (e < E) atomicAdd(&g_cnt[ei[E + e]], 1);
}

__global__ void k_dinv(int n) {
    int i = blockIdx.x * blockDim.x + threadIdx.x;
    if (i < n) g_dinv[i] = rsqrtf((float)g_cnt[i] + 1.0f);
}

// ---------------------------------------------------------------------------
// GEMM h' = (x @ W) * dinv, fp32 f32x2 FFMA, conflict-free smem mappings.
// Thread owns rows tmr..tmr+7, cols [tnc..tnc+3] and [64+tnc..64+tnc+3].
#define BM 64
#define BN 128
#define BK 16
#define TM 8

__global__ __launch_bounds__(128) void k_gemm(const float* __restrict__ X,
                                              const float* __restrict__ W,
                                              int M) {
    __shared__ float Ast[BK][BM + 4];
    __shared__ float Bs[BK][BN];

    int tid = threadIdx.x;
    int m0  = blockIdx.x * BM;
    int tmr = (tid >> 4) * TM;       // 0,8,...,56
    int tnc = (tid & 15) * 4;        // 0,4,...,60  (conflict-free B reads)

    unsigned long long acc[TM][4];
#pragma unroll
    for (int i = 0; i < TM; i++)
#pragma unroll
        for (int j = 0; j < 4; j++) acc[i][j] = 0ULL;

    for (int k0 = 0; k0 < NFEAT; k0 += BK) {
#pragma unroll
        for (int j = 0; j < 2; j++) {
            int idx = tid + j * 128;
            int r   = idx >> 2;
            int c4  = idx & 3;
            float4 v = make_float4(0.f, 0.f, 0.f, 0.f);
            int gr = m0 + r;
            if (gr < M)
                v = *(const float4*)(X + (size_t)gr * NFEAT + k0 + c4 * 4);
            Ast[c4 * 4 + 0][r] = v.x;
            Ast[c4 * 4 + 1][r] = v.y;
            Ast[c4 * 4 + 2][r] = v.z;
            Ast[c4 * 4 + 3][r] = v.w;
        }
#pragma unroll
        for (int j = 0; j < 4; j++) {
            int idx = tid + j * 128;
            int r   = idx >> 5;
            int c4  = idx & 31;
            *(float4*)&Bs[r][c4 * 4] =
                *(const float4*)(W + (size_t)(k0 + r) * NFEAT + c4 * 4);
        }
        __syncthreads();

#pragma unroll
        for (int k = 0; k < BK; k++) {
            float4 a0 = *(const float4*)&Ast[k][tmr];
            float4 a1 = *(const float4*)&Ast[k][tmr + 4];
            float4 b0 = *(const float4*)&Bs[k][tnc];        // contiguous per warp
            float4 b1 = *(const float4*)&Bs[k][64 + tnc];   // contiguous per warp

            unsigned long long apair[TM];
            float av[TM] = {a0.x, a0.y, a0.z, a0.w, a1.x, a1.y, a1.z, a1.w};
#pragma unroll
            for (int i = 0; i < TM; i++)
                asm("mov.b64 %0, {%1,%1};" : "=l"(apair[i]) : "f"(av[i]));

            unsigned long long bpair[4];
            asm("mov.b64 %0, {%1,%2};" : "=l"(bpair[0]) : "f"(b0.x), "f"(b0.y));
            asm("mov.b64 %0, {%1,%2};" : "=l"(bpair[1]) : "f"(b0.z), "f"(b0.w));
            asm("mov.b64 %0, {%1,%2};" : "=l"(bpair[2]) : "f"(b1.x), "f"(b1.y));
            asm("mov.b64 %0, {%1,%2};" : "=l"(bpair[3]) : "f"(b1.z), "f"(b1.w));

#pragma unroll
            for (int i = 0; i < TM; i++)
#pragma unroll
                for (int j = 0; j < 4; j++)
                    asm("fma.rn.f32x2 %0, %1, %2, %0;"
                        : "+l"(acc[i][j])
                        : "l"(apair[i]), "l"(bpair[j]));
        }
        __syncthreads();
    }

#pragma unroll
    for (int i = 0; i < TM; i++) {
        int gr = m0 + tmr + i;
        if (gr < M) {
            float dv = g_dinv[gr];
            float o[8];
#pragma unroll
            for (int j = 0; j < 4; j++)
                asm("mov.b64 {%0,%1}, %2;" : "=f"(o[2 * j]), "=f"(o[2 * j + 1])
                    : "l"(acc[i][j]));
            __half2 p0 = __floats2half2_rn(o[0] * dv, o[1] * dv);
            __half2 p1 = __floats2half2_rn(o[2] * dv, o[3] * dv);
            __half2 p2 = __floats2half2_rn(o[4] * dv, o[5] * dv);
            __half2 p3 = __floats2half2_rn(o[6] * dv, o[7] * dv);
            __half2* rowp = g_hh + (size_t)gr * (NFEAT / 2);
            uint2 u0, u1;
            u0.x = *(unsigned*)&p0; u0.y = *(unsigned*)&p1;
            u1.x = *(unsigned*)&p2; u1.y = *(unsigned*)&p3;
            *(uint2*)(rowp + (tnc >> 1))        = u0;  // cols tnc..tnc+3
            *(uint2*)(rowp + ((64 + tnc) >> 1)) = u1;  // cols 64+tnc..
        }
    }
}

// ---------------------------------------------------------------------------
// Warp-shuffle scans
__global__ void k_scan1(int n) {
    __shared__ int ws[8];
    int t = threadIdx.x, lane = t & 31, wid = t >> 5;
    int i = blockIdx.x * 256 + t;
    int x = (i < n) ? g_cnt[i] : 0;
#pragma unroll
    for (int ofs = 1; ofs < 32; ofs <<= 1) {
        int y = __shfl_up_sync(0xffffffffu, x, ofs);
        if (lane >= ofs) x += y;
    }
    if (lane == 31) ws[wid] = x;
    __syncthreads();
    if (wid == 0) {
        int y = (lane < 8) ? ws[lane] : 0;
#pragma unroll
        for (int ofs = 1; ofs < 8; ofs <<= 1) {
            int z = __shfl_up_sync(0xffffffffu, y, ofs);
            if (lane >= ofs) y += z;
        }
        if (lane < 8) ws[lane] = y;
    }
    __syncthreads();
    int incl = x + (wid > 0 ? ws[wid - 1] : 0);
    if (i < n) g_scan[i] = incl;
    if (t == 255) g_part[blockIdx.x] = incl;
}

__global__ void k_scan2(int nb) {
    __shared__ int ws[16];
    int t = threadIdx.x, lane = t & 31, wid = t >> 5;
    int x = (t < nb) ? g_part[t] : 0;
#pragma unroll
    for (int ofs = 1; ofs < 32; ofs <<= 1) {
        int y = __shfl_up_sync(0xffffffffu, x, ofs);
        if (lane >= ofs) x += y;
    }
    if (lane == 31) ws[wid] = x;
    __syncthreads();
    if (wid == 0) {
        int y = (lane < 16) ? ws[lane] : 0;
#pragma unroll
        for (int ofs = 1; ofs < 16; ofs <<= 1) {
            int z = __shfl_up_sync(0xffffffffu, y, ofs);
            if (lane >= ofs) y += z;
        }
        if (lane < 16) ws[lane] = y;
    }
    __syncthreads();
    int incl = x + (wid > 0 ? ws[wid - 1] : 0);
    if (t < nb) g_part[t] = incl;
}

__global__ void k_scan3(int n) {
    int i = blockIdx.x * blockDim.x + threadIdx.x;
    if (i >= n) return;
    int b = i >> 8;
    int off = g_scan[i] - g_cnt[i] + (b > 0 ? g_part[b - 1] : 0);
    g_off[i] = off;
    g_cursor[i] = off;
}

__global__ void k_csr4(const int* __restrict__ ei, int E) {
    int e4 = blockIdx.x * blockDim.x + threadIdx.x;
    if (e4 * 4 >= E) return;
    int4 s = ((const int4*)ei)[e4];
    int4 d = ((const int4*)(ei + E))[e4];
    g_csr[atomicAdd(&g_cursor[d.x], 1)] = s.x;
    g_csr[atomicAdd(&g_cursor[d.y], 1)] = s.y;
    g_csr[atomicAdd(&g_cursor[d.z], 1)] = s.z;
    g_csr[atomicAdd(&g_cursor[d.w], 1)] = s.w;
}
__global__ void k_csr1(const int* __restrict__ ei, int E) {
    int e = blockIdx.x * blockDim.x + threadIdx.x;
    if (e >= E) return;
    g_csr[atomicAdd(&g_cursor[ei[E + e]], 1)] = ei[e];
}

// ---------------------------------------------------------------------------
// Gather: one warp per dst node, fp16 rows (256 B), fp32 accumulation.
// out = (sum_src h'[src] + h'[node]) * dinv[node] + b
__global__ __launch_bounds__(256) void k_gather(const float* __restrict__ b,
                                                float* __restrict__ out, int N) {
    int node = blockIdx.x * 8 + (threadIdx.x >> 5);
    if (node >= N) return;
    int lane = threadIdx.x & 31;

    int base = g_off[node];
    int cnt  = g_cnt[node];
    float dd = g_dinv[node];

    float4 acc;
    {
        uint2 u = ((const uint2*)(g_hh + (size_t)node * (NFEAT / 2)))[lane];
        float2 f0 = __half22float2(*(__half2*)&u.x);
        float2 f1 = __half22float2(*(__half2*)&u.y);
        acc = make_float4(f0.x, f0.y, f1.x, f1.y);
    }

    int i = 0;
    for (; i + 4 <= cnt; i += 4) {
        int s0 = g_csr[base + i];
        int s1 = g_csr[base + i + 1];
        int s2 = g_csr[base + i + 2];
        int s3 = g_csr[base + i + 3];
        uint2 u0 = ((const uint2*)(g_hh + (size_t)s0 * (NFEAT / 2)))[lane];
        uint2 u1 = ((const uint2*)(g_hh + (size_t)s1 * (NFEAT / 2)))[lane];
        uint2 u2 = ((const uint2*)(g_hh + (size_t)s2 * (NFEAT / 2)))[lane];
        uint2 u3 = ((const uint2*)(g_hh + (size_t)s3 * (NFEAT / 2)))[lane];
        float2 a0 = __half22float2(*(__half2*)&u0.x), a1 = __half22float2(*(__half2*)&u0.y);
        float2 c0 = __half22float2(*(__half2*)&u1.x), c1 = __half22float2(*(__half2*)&u1.y);
        float2 d0 = __half22float2(*(__half2*)&u2.x), d1 = __half22float2(*(__half2*)&u2.y);
        float2 e0 = __half22float2(*(__half2*)&u3.x), e1 = __half22float2(*(__half2*)&u3.y);
        acc.x += a0.x + c0.x + d0.x + e0.x;
        acc.y += a0.y + c0.y + d0.y + e0.y;
        acc.z += a1.x + c1.x + d1.x + e1.x;
        acc.w += a1.y + c1.y + d1.y + e1.y;
    }
    for (; i < cnt; i++) {
        int s0 = g_csr[base + i];
        uint2 u0 = ((const uint2*)(g_hh + (size_t)s0 * (NFEAT / 2)))[lane];
        float2 a0 = __half22float2(*(__half2*)&u0.x), a1 = __half22float2(*(__half2*)&u0.y);
        acc.x += a0.x; acc.y += a0.y; acc.z += a1.x; acc.w += a1.y;
    }

    float4 bv = ((const float4*)b)[lane];
    float4 o;
    o.x = bv.x + acc.x * dd;
    o.y = bv.y + acc.y * dd;
    o.z = bv.z + acc.z * dd;
    o.w = bv.w + acc.w * dd;
    ((float4*)(out + (size_t)node * NFEAT))[lane] = o;
}

// ---------------------------------------------------------------------------
extern "C" void kernel_launch(void* const* d_in, const int* in_sizes, int n_in,
                              void* d_out, int out_size) {
    const float* x  = (const float*)d_in[0];
    const int*   ei = (const int*)d_in[1];
    const float* w  = (const float*)d_in[2];
    const float* b  = (const float*)d_in[3];
    float* out = (float*)d_out;

    int N = in_sizes[0] / NFEAT;
    int E = in_sizes[1] / 2;
    int NB = (N + 255) / 256;

    k_zero_cnt<<<(N + 255) / 256, 256>>>(N);
    if ((E & 3) == 0)
        k_count4<<<(E / 4 + 255) / 256, 256>>>(ei, E);
    else
        k_count1<<<(E + 255) / 256, 256>>>(ei, E);
    k_dinv<<<(N + 255) / 256, 256>>>(N);
    k_gemm<<<(N + BM - 1) / BM, 128>>>(x, w, N);   // launch idx 3 -> profiled
    k_scan1<<<NB, 256>>>(N);
    k_scan2<<<1, 512>>>(NB);
    k_scan3<<<(N + 255) / 256, 256>>>(N);
    if ((E & 3) == 0)
        k_csr4<<<(E / 4 + 255) / 256, 256>>>(ei, E);
    else
        k_csr1<<<(E + 255) / 256, 256>>>(ei, E);
    k_gather<<<(N + 7) / 8, 256>>>(b, out, N);
}